// round 13
// baseline (speedup 1.0000x reference)
#include <cuda_runtime.h>
#include <cuda_fp16.h>
#include <cstdint>

// Problem (fixed): B=4,N=2048,Fin=128,H=4,Fout=32.
// Identity: softmax(scores,m).sum(m)==1  =>  out = (1+self_weight)*(x @ W).
// adj, att are dead inputs.
//
// R13: single-term fp16 HMMA (R12 math: out ~= fp16(x) @ fp16(W), fp32 acc,
// rel_err 2.9e-4), restructured as a persistent 148-block grid:
//  - block b: col0=(b&1)*64; row tiles j=b>>1 and (74+j) (second if j<54)
//  - W staged/converted ONCE per block (R12 re-staged it on 108 dual SMs)
//  - A double-buffered: all 24 LDG.128 issued up front; A1 convert+STS after
//    tile-0 epilogue, its latency hidden under tile-0 compute
//  - exactly 1 block/SM -> balanced wave, halved L1tex queue pressure

#define MDIM 8192
#define KDIM 128
#define NDIM 128
#define TM 64
#define TN 64
#define ASTRIDE 272   // A smem row: 128 fp16 = 256B data + 16 pad
#define BSTRIDE 144   // B smem row: 64 fp16 = 128B data + 16 pad

#define SMEM_A0 0
#define SMEM_A1 (SMEM_A0 + TM * ASTRIDE)        // 17408
#define SMEM_B  (SMEM_A1 + TM * ASTRIDE)        // 34816
#define SMEM_TOTAL (SMEM_B + KDIM * BSTRIDE)    // 53248

__device__ __forceinline__ uint32_t smem_u32(const void* p) {
    uint32_t a;
    asm("{ .reg .u64 t; cvta.to.shared.u64 t, %1; cvt.u32.u64 %0, t; }"
        : "=r"(a) : "l"(p));
    return a;
}

__device__ __forceinline__ void ldsm4(uint32_t r[4], uint32_t addr) {
    asm volatile("ldmatrix.sync.aligned.m8n8.x4.shared.b16 {%0,%1,%2,%3}, [%4];"
                 : "=r"(r[0]), "=r"(r[1]), "=r"(r[2]), "=r"(r[3]) : "r"(addr));
}
__device__ __forceinline__ void ldsm4t(uint32_t r[4], uint32_t addr) {
    asm volatile("ldmatrix.sync.aligned.m8n8.x4.trans.shared.b16 {%0,%1,%2,%3}, [%4];"
                 : "=r"(r[0]), "=r"(r[1]), "=r"(r[2]), "=r"(r[3]) : "r"(addr));
}

__device__ __forceinline__ void mma_f16(float c[4], const uint32_t a[4],
                                        uint32_t b0, uint32_t b1) {
    asm volatile(
        "mma.sync.aligned.m16n8k16.row.col.f32.f16.f16.f32 "
        "{%0,%1,%2,%3}, {%4,%5,%6,%7}, {%8,%9}, {%0,%1,%2,%3};"
        : "+f"(c[0]), "+f"(c[1]), "+f"(c[2]), "+f"(c[3])
        : "r"(a[0]), "r"(a[1]), "r"(a[2]), "r"(a[3]), "r"(b0), "r"(b1));
}

__device__ __forceinline__ uint32_t h2_pack(float a, float b) {
    __half2 h = __float22half2_rn(make_float2(a, b));
    return *reinterpret_cast<uint32_t*>(&h);
}
__device__ __forceinline__ uint2 cvt4(const float4& f) {
    uint2 r;
    r.x = h2_pack(f.x, f.y);
    r.y = h2_pack(f.z, f.w);
    return r;
}

// compute one 64x64 tile from smem A (at aoff) x smem B, write scaled output
__device__ __forceinline__ void compute_tile(
    const uint32_t sbase, const uint32_t aoff,
    const int row0, const int col0, const int wid, const int lid,
    const float s, float* __restrict__ out)
{
    const int wm = (wid >> 1) * 16;     // 0,16,32,48
    const int wn = (wid & 1) * 32;      // 0,32

    float acc[4][4];
    #pragma unroll
    for (int j = 0; j < 4; j++)
        #pragma unroll
        for (int e = 0; e < 4; e++) acc[j][e] = 0.f;

    const uint32_t aAddr = sbase + aoff
        + (wm + (lid & 15)) * ASTRIDE + 16 * (lid >> 4);
    uint32_t bAddr[2];
    #pragma unroll
    for (int p = 0; p < 2; p++)
        bAddr[p] = sbase + SMEM_B
            + (8 * ((lid >> 3) & 1) + (lid & 7)) * BSTRIDE
            + (wn + 16 * p + 8 * (lid >> 4)) * 2;

    #pragma unroll
    for (int ks = 0; ks < 8; ks++) {
        const uint32_t ako = ks * 32;
        const uint32_t bko = ks * 16 * BSTRIDE;

        uint32_t ah[4];
        ldsm4(ah, aAddr + ako);
        uint32_t bh[2][4];
        #pragma unroll
        for (int p = 0; p < 2; p++)
            ldsm4t(bh[p], bAddr[p] + bko);

        #pragma unroll
        for (int nt = 0; nt < 4; nt++) {
            const int p = nt >> 1, q = (nt & 1) * 2;
            mma_f16(acc[nt], ah, bh[p][q], bh[p][q + 1]);
        }
    }

    #pragma unroll
    for (int nt = 0; nt < 4; nt++) {
        const int r0 = row0 + wm + (lid >> 2);
        const int c  = col0 + wn + 8 * nt + 2 * (lid & 3);
        float2 s0 = {acc[nt][0] * s, acc[nt][1] * s};
        float2 s1 = {acc[nt][2] * s, acc[nt][3] * s};
        *(float2*)&out[(size_t)r0 * NDIM + c]       = s0;
        *(float2*)&out[(size_t)(r0 + 8) * NDIM + c] = s1;
    }
}

__global__ __launch_bounds__(256, 1)
void gat_hmma_kernel(const float* __restrict__ x,
                     const float* __restrict__ W,
                     const float* __restrict__ self_weight,
                     float* __restrict__ out) {
    extern __shared__ char smem[];
    const uint32_t sbase = smem_u32(smem);
    const int tid = threadIdx.x;
    const int wid = tid >> 5;
    const int lid = tid & 31;

    const int bid  = blockIdx.x;          // 0..147
    const int j    = bid >> 1;            // 0..73
    const int col0 = (bid & 1) * TN;      // 0 or 64
    const int row0 = j * TM;
    const int row1 = (74 + j) * TM;
    const bool has2 = (j < 54);           // second tile exists (rows 74..127)

    const float s = 1.0f + self_weight[0];

    // ---- issue ALL global loads up front (W 8 + A0 8 + A1 8 = 24 LDG.128) ----
    float4 fb[8], fa0[8], fa1[8];
    #pragma unroll
    for (int r = 0; r < 8; r++) {
        int g  = tid + r * 256;
        int k  = g >> 4;                  // 0..127
        int n4 = g & 15;
        fb[r] = *(const float4*)&W[(size_t)k * NDIM + col0 + n4 * 4];
    }
    #pragma unroll
    for (int r = 0; r < 8; r++) {
        int g  = tid + r * 256;
        int m  = g >> 5;                  // 0..63
        int k4 = g & 31;
        fa0[r] = *(const float4*)&x[(size_t)(row0 + m) * KDIM + k4 * 4];
    }
    if (has2) {
        #pragma unroll
        for (int r = 0; r < 8; r++) {
            int g  = tid + r * 256;
            int m  = g >> 5;
            int k4 = g & 31;
            fa1[r] = *(const float4*)&x[(size_t)(row1 + m) * KDIM + k4 * 4];
        }
    }

    // ---- convert + store B (once per block) and A0 ----
    #pragma unroll
    for (int r = 0; r < 8; r++) {
        int g  = tid + r * 256;
        int k  = g >> 4;
        int n4 = g & 15;
        *(uint2*)(smem + SMEM_B + k * BSTRIDE + n4 * 8) = cvt4(fb[r]);
    }
    #pragma unroll
    for (int r = 0; r < 8; r++) {
        int g  = tid + r * 256;
        int m  = g >> 5;
        int k4 = g & 31;
        *(uint2*)(smem + SMEM_A0 + m * ASTRIDE + k4 * 8) = cvt4(fa0[r]);
    }
    __syncthreads();

    // ---- tile 0 ----
    compute_tile(sbase, SMEM_A0, row0, col0, wid, lid, s, out);

    // ---- tile 1 (A1 loads have been in flight since the top) ----
    if (has2) {
        #pragma unroll
        for (int r = 0; r < 8; r++) {
            int g  = tid + r * 256;
            int m  = g >> 5;
            int k4 = g & 31;
            *(uint2*)(smem + SMEM_A1 + m * ASTRIDE + k4 * 8) = cvt4(fa1[r]);
        }
        __syncthreads();
        compute_tile(sbase, SMEM_A1, row1, col0, wid, lid, s, out);
    }
}

extern "C" void kernel_launch(void* const* d_in, const int* in_sizes, int n_in,
                              void* d_out, int out_size) {
    // metadata order: x, adj (UNUSED), W, att (UNUSED), self_weight
    const float* x  = (const float*)d_in[0];
    const float* W  = (const float*)d_in[2];
    const float* sw = (const float*)d_in[4];
    float* out      = (float*)d_out;

    cudaFuncSetAttribute(gat_hmma_kernel,
                         cudaFuncAttributeMaxDynamicSharedMemorySize, SMEM_TOTAL);

    gat_hmma_kernel<<<148, 256, SMEM_TOTAL>>>(x, W, sw, out);
}